// round 3
// baseline (speedup 1.0000x reference)
#include <cuda_runtime.h>
#include <math.h>

#define BB 64
#define LL 8192
#define DD 64
#define NCHUNK 32
#define CHUNK (LL / NCHUNK)   // 256 rows per chunk

// Scratch (allocation-free rule: __device__ globals)
__device__ float g_pm[BB * NCHUNK];            // partial max
__device__ float g_ps[BB * NCHUNK];            // partial sumexp
__device__ float g_pv[BB * NCHUNK * DD];       // partial weighted v-sum
__device__ float g_attn[BB * DD];              // final collect vector

// ---------------------------------------------------------------------------
// Pass 1: logits + online-softmax partials per (batch, chunk)
// grid = BB*NCHUNK blocks, 256 threads
// float4 loads: one LDG.128 covers 2 rows (16 lanes x 16B per row)
// ---------------------------------------------------------------------------
__global__ __launch_bounds__(256) void collect_partial_kernel(
    const float* __restrict__ q,
    const float* __restrict__ kc,
    const float* __restrict__ v,
    const float* __restrict__ tc_p,
    float* __restrict__ logits_out)
{
    const int b = blockIdx.x / NCHUNK;
    const int c = blockIdx.x % NCHUNK;
    const int l0 = c * CHUNK;
    const int t = threadIdx.x;
    const int warp = t >> 5;
    const int lane = t & 31;
    const int lane15 = lane & 15;
    const int half = lane >> 4;

    __shared__ float sq[DD];
    __shared__ float slogit[CHUNK];
    __shared__ float sw[CHUNK];
    __shared__ float red[8];
    __shared__ float red2[8];
    __shared__ float svs[8][DD];

    if (t < DD) sq[t] = q[b * DD + t];
    __syncthreads();

    const float inv_tc = 1.0f / tc_p[0];
    const float4 qv = ((const float4*)sq)[lane15];

    // 2 rows per LDG.128: lanes 0-15 -> even row, 16-31 -> odd row
    float local_max = -INFINITY;
    const float4* kc4 = (const float4*)(kc + ((size_t)b * LL + l0) * DD);
    #pragma unroll 2
    for (int j = warp; j < CHUNK / 2; j += 8) {
        const int r = 2 * j + half;
        const float4 a = __ldcs(kc4 + (size_t)r * (DD / 4) + lane15);
        float p = a.x * qv.x + a.y * qv.y + a.z * qv.z + a.w * qv.w;
        #pragma unroll
        for (int o = 8; o; o >>= 1) p += __shfl_xor_sync(0xffffffffu, p, o);
        const float lg = p * inv_tc;
        if (lane15 == 0) slogit[r] = lg;
        local_max = fmaxf(local_max, lg);
    }
    // block max
    #pragma unroll
    for (int o = 16; o; o >>= 1)
        local_max = fmaxf(local_max, __shfl_xor_sync(0xffffffffu, local_max, o));
    if (lane == 0) red[warp] = local_max;
    __syncthreads();
    float m = red[0];
    #pragma unroll
    for (int i = 1; i < 8; i++) m = fmaxf(m, red[i]);

    // write logits (coalesced: CHUNK == blockDim), streaming store
    const float lg = slogit[t];
    __stcs(logits_out + (size_t)b * LL + l0 + t, lg);

    // exp weights + block sumexp
    const float e = __expf(lg - m);
    sw[t] = e;
    float se = e;
    #pragma unroll
    for (int o = 16; o; o >>= 1) se += __shfl_xor_sync(0xffffffffu, se, o);
    if (lane == 0) red2[warp] = se;
    __syncthreads();
    float sum_e = 0.0f;
    #pragma unroll
    for (int i = 0; i < 8; i++) sum_e += red2[i];

    // weighted v-sum: thread (g, lane) handles 2 consecutive d via float2
    // g = row-group 0..7, d = 2*lane
    const int g = t >> 5;        // 0..7
    const float2* v2 = (const float2*)(v + ((size_t)b * LL + l0) * DD);
    float2 acc = make_float2(0.0f, 0.0f);
    #pragma unroll 8
    for (int r = g; r < CHUNK; r += 8) {
        const float2 vv = __ldcs(v2 + (size_t)r * (DD / 2) + lane);
        const float w = sw[r];
        acc.x += w * vv.x;
        acc.y += w * vv.y;
    }
    svs[g][2 * lane]     = acc.x;
    svs[g][2 * lane + 1] = acc.y;
    __syncthreads();

    if (t < DD) {
        float vs = svs[0][t];
        #pragma unroll
        for (int i = 1; i < 8; i++) vs += svs[i][t];
        g_pv[((size_t)b * NCHUNK + c) * DD + t] = vs;
    }
    if (t == 0) {
        g_pm[b * NCHUNK + c] = m;
        g_ps[b * NCHUNK + c] = sum_e;
    }
}

// ---------------------------------------------------------------------------
// Pass 2: combine chunk partials -> attn[b][d]
// grid = BB blocks, DD threads
// ---------------------------------------------------------------------------
__global__ __launch_bounds__(DD) void combine_kernel()
{
    const int b = blockIdx.x;
    const int d = threadIdx.x;

    float M = -INFINITY;
    #pragma unroll 8
    for (int c = 0; c < NCHUNK; c++)
        M = fmaxf(M, g_pm[b * NCHUNK + c]);

    float Z = 0.0f, acc = 0.0f;
    #pragma unroll 8
    for (int c = 0; c < NCHUNK; c++) {
        const float sc = __expf(g_pm[b * NCHUNK + c] - M);
        Z += g_ps[b * NCHUNK + c] * sc;
        acc += g_pv[((size_t)b * NCHUNK + c) * DD + d] * sc;
    }
    g_attn[b * DD + d] = acc / Z;
}

// ---------------------------------------------------------------------------
// Pass 3: diffuse gate * attn, streamed.
// 256 threads = 8 warps; each warp handles 8 rows (2 rows per LDG.128)
// grid = BB * LL / 64 blocks
// ---------------------------------------------------------------------------
#define ROWS_PER_WARP 8
#define ROWS_PER_BLOCK (8 * ROWS_PER_WARP)   // 64
#define BLOCKS_PER_BATCH (LL / ROWS_PER_BLOCK)

__global__ __launch_bounds__(256) void diffuse_kernel(
    const float* __restrict__ q,
    const float* __restrict__ kd,
    const float* __restrict__ td_p,
    float* __restrict__ out)
{
    const int b = blockIdx.x / BLOCKS_PER_BATCH;
    const int rb = blockIdx.x % BLOCKS_PER_BATCH;
    const int t = threadIdx.x;
    const int warp = t >> 5;
    const int lane = t & 31;
    const int lane15 = lane & 15;
    const int half = lane >> 4;

    __shared__ float sq[DD];
    __shared__ float sa[DD];
    if (t < DD) {
        sq[t] = q[b * DD + t];
        sa[t] = g_attn[b * DD + t];
    }
    __syncthreads();

    const float inv_td = 1.0f / td_p[0];
    const float4 qv = ((const float4*)sq)[lane15];
    const float4 av = ((const float4*)sa)[lane15];

    const int l_base = rb * ROWS_PER_BLOCK + warp * ROWS_PER_WARP;
    const size_t row0 = ((size_t)b * LL + l_base) * DD;
    const float4* kd4 = (const float4*)(kd + row0);

    // 4 LDG.128 per warp cover 8 rows (lanes 0-15 even row, 16-31 odd row)
    float4 a0 = __ldcs(kd4 + (size_t)(0 + half) * (DD / 4) + lane15);
    float4 a1 = __ldcs(kd4 + (size_t)(2 + half) * (DD / 4) + lane15);
    float4 a2 = __ldcs(kd4 + (size_t)(4 + half) * (DD / 4) + lane15);
    float4 a3 = __ldcs(kd4 + (size_t)(6 + half) * (DD / 4) + lane15);

    float p0 = a0.x * qv.x + a0.y * qv.y + a0.z * qv.z + a0.w * qv.w;
    float p1 = a1.x * qv.x + a1.y * qv.y + a1.z * qv.z + a1.w * qv.w;
    float p2 = a2.x * qv.x + a2.y * qv.y + a2.z * qv.z + a2.w * qv.w;
    float p3 = a3.x * qv.x + a3.y * qv.y + a3.z * qv.z + a3.w * qv.w;
    #pragma unroll
    for (int o = 8; o; o >>= 1) {
        p0 += __shfl_xor_sync(0xffffffffu, p0, o);
        p1 += __shfl_xor_sync(0xffffffffu, p1, o);
        p2 += __shfl_xor_sync(0xffffffffu, p2, o);
        p3 += __shfl_xor_sync(0xffffffffu, p3, o);
    }
    const float g0 = 1.0f / (1.0f + __expf(-p0 * inv_td));
    const float g1 = 1.0f / (1.0f + __expf(-p1 * inv_td));
    const float g2 = 1.0f / (1.0f + __expf(-p2 * inv_td));
    const float g3 = 1.0f / (1.0f + __expf(-p3 * inv_td));

    float4* out4 = (float4*)(out + row0);
    __stcs(out4 + (size_t)(0 + half) * (DD / 4) + lane15,
           make_float4(g0 * av.x, g0 * av.y, g0 * av.z, g0 * av.w));
    __stcs(out4 + (size_t)(2 + half) * (DD / 4) + lane15,
           make_float4(g1 * av.x, g1 * av.y, g1 * av.z, g1 * av.w));
    __stcs(out4 + (size_t)(4 + half) * (DD / 4) + lane15,
           make_float4(g2 * av.x, g2 * av.y, g2 * av.z, g2 * av.w));
    __stcs(out4 + (size_t)(6 + half) * (DD / 4) + lane15,
           make_float4(g3 * av.x, g3 * av.y, g3 * av.z, g3 * av.w));
}

// ---------------------------------------------------------------------------
extern "C" void kernel_launch(void* const* d_in, const int* in_sizes, int n_in,
                              void* d_out, int out_size)
{
    const float* q  = (const float*)d_in[0];
    const float* kc = (const float*)d_in[1];
    const float* kd = (const float*)d_in[2];
    const float* v  = (const float*)d_in[3];
    const float* tc = (const float*)d_in[4];
    const float* td = (const float*)d_in[5];

    float* out    = (float*)d_out;                        // [B, L, D]
    float* logits = (float*)d_out + (size_t)BB * LL * DD; // [B, L]

    collect_partial_kernel<<<BB * NCHUNK, 256>>>(q, kc, v, tc, logits);
    combine_kernel<<<BB, DD>>>();
    diffuse_kernel<<<BB * BLOCKS_PER_BATCH, 256>>>(q, kd, td, out);
}